// round 1
// baseline (speedup 1.0000x reference)
#include <cuda_runtime.h>
#include <cuda_bf16.h>
#include <math.h>

// Problem constants (from reference)
#define TT   1024
#define DD   4
#define PP   8
#define DPW  32            // D*P
#define SS   256           // N * N_SAMPLE
#define NCHUNK 32          // chunks along t
#define LCHUNK 32          // t per chunk
#define TBL  (TT*DPW)      // 32768 table elements
#define SZ   ((size_t)SS*TT*DPW)  // 8388608 elements per output tensor

// Precomputed per-(t, d_out, p) tables (allocation-free scratch)
__device__ float g_mean[TBL];
__device__ float g_sw[TBL];
__device__ float g_c0[TBL];
__device__ float g_amul[TT*DD];   // recursion multiplier a[t-1,d], amul[0]=0

// ---------------------------------------------------------------------------
// Kernel 1: precompute tables (tiny, one-shot per launch)
// ---------------------------------------------------------------------------
__global__ void arma_precompute(const float* __restrict__ m,
                                const float* __restrict__ s_raw,
                                const float* __restrict__ a_raw,
                                const int*   __restrict__ dim_idx)
{
    int idx = blockIdx.x * blockDim.x + threadIdx.x;
    if (idx >= TBL) return;
    int t  = idx >> 5;          // 0..1023
    int dp = idx & 31;
    int dd = dp >> 3;           // output dim 0..3
    int p  = dp & 7;
    int src = dim_idx[dd];      // source dim (identity in this dataset, but honor it)

    // amul[t] = sigmoid(a_raw[t-1, src]) for t>=1, else 0
    float am = 0.0f;
    if (t > 0) {
        float x = a_raw[(t - 1) * DD + src];
        am = 1.0f / (1.0f + expf(-x));
    }

    float sv = s_raw[t * DPW + src * PP + p];
    float sw = (sv > 20.0f) ? sv : log1pf(expf(sv));     // softplus, accurate
    float mn = (1.0f - am) * m[t * DPW + src * PP + p];

    g_mean[idx] = mn;
    g_sw[idx]   = sw;
    g_c0[idx]   = -logf(sw) - 0.91893853320467274178f;   // -log(sw) - 0.5*log(2*pi)
    if (p == 0) g_amul[t * DD + dd] = am;
}

// ---------------------------------------------------------------------------
// Kernel 2: main streaming scan. One block per sample s.
// 1024 threads = 32 chunks (c = tid>>5) x 32 chains (dp = tid&31).
// Phase 1: stream noise, compute z (kept in regs), lp (stored), and the
//          per-chunk affine summary (A = prod a, b = local recursion end).
// Phase 2: 32-thread serial scan over chunk summaries per chain (cheap).
// Phase 3: replay recursion with the correct carry, store param.
// All global accesses are 128B-coalesced (dp in low lane bits).
// ---------------------------------------------------------------------------
__global__ void __launch_bounds__(1024, 1)
arma_main(const float* __restrict__ noise,
          float* __restrict__ out_param,
          float* __restrict__ out_lp,
          int write_lp)
{
    const int s   = blockIdx.x;
    const int tid = threadIdx.x;
    const int dp  = tid & 31;
    const int c   = tid >> 5;
    const int dd  = dp >> 3;

    __shared__ float sa[TT * DD];        // amul table, 16 KB
    __shared__ float sA[NCHUNK][DPW];    // chunk product of a
    __shared__ float sB[NCHUNK][DPW];    // chunk local end value
    __shared__ float sC[NCHUNK][DPW];    // exclusive carry per chunk

    for (int i = tid; i < TT * DD; i += 1024) sa[i] = g_amul[i];
    __syncthreads();

    const float* np = noise     + ((size_t)s << 15);   // s * T * 32
    float*       pp = out_param + ((size_t)s << 15);
    float*       lq = out_lp    + ((size_t)s << 15);

    const int t0 = c << 5;

    float z[LCHUNK];
    float A = 1.0f, b = 0.0f;

#pragma unroll
    for (int i = 0; i < LCHUNK; i++) {
        const int t   = t0 + i;
        const int off = (t << 5) + dp;
        const float n  = __ldcs(np + off);
        const float zz = fmaf(g_sw[off], n, g_mean[off]);
        z[i] = zz;
        if (write_lp) {
            __stcs(lq + off, fmaf(-0.5f * n, n, g_c0[off]));
        }
        const float am = sa[(t << 2) + dd];
        A *= am;                       // for chunk 0, amul[0]=0 zeroes A (correct)
        b = fmaf(am, b, zz);
    }

    sA[c][dp] = A;
    sB[c][dp] = b;
    __syncthreads();

    // Serial affine scan over the 32 chunks of each chain; 32 scanner threads
    // (one per dp), conflict-free smem rows. ~32 iters, negligible cost.
    if (tid < 32) {
        float run = 0.0f;
#pragma unroll
        for (int cc = 0; cc < NCHUNK; cc++) {
            sC[cc][tid] = run;                       // exclusive carry
            run = fmaf(sA[cc][tid], run, sB[cc][tid]);
        }
    }
    __syncthreads();

    // Replay with correct carry-in; z from registers, amul from smem.
    float pv = sC[c][dp];
#pragma unroll
    for (int i = 0; i < LCHUNK; i++) {
        const int t = t0 + i;
        pv = fmaf(sa[(t << 2) + dd], pv, z[i]);
        __stcs(pp + (t << 5) + dp, pv);
    }
}

// ---------------------------------------------------------------------------
// Launch
// Inputs (metadata order): 0:y 1:age 2:m 3:s_raw 4:a_raw 5:noise
//                          6:cond_sample 7:dim_idx 8:compute_log_prob
// Output: param (S,T,D,P) then log_prob (S,T,D,P), float32.
// ---------------------------------------------------------------------------
extern "C" void kernel_launch(void* const* d_in, const int* in_sizes, int n_in,
                              void* d_out, int out_size)
{
    const float* m      = (const float*)d_in[2];
    const float* s_raw  = (const float*)d_in[3];
    const float* a_raw  = (const float*)d_in[4];
    const float* noise  = (const float*)d_in[5];
    const int*   dimidx = (const int*)  d_in[7];

    float* out_param = (float*)d_out;
    int write_lp = (out_size >= (int)(2 * SZ)) ? 1 : 0;
    float* out_lp = out_param + SZ;   // valid region only if write_lp

    arma_precompute<<<(TBL + 255) / 256, 256>>>(m, s_raw, a_raw, dimidx);
    arma_main<<<SS, 1024>>>(noise, out_param, write_lp ? out_lp : out_param, write_lp);
}

// round 2
// speedup vs baseline: 1.1252x; 1.1252x over previous
#include <cuda_runtime.h>
#include <cuda_bf16.h>
#include <math.h>

// Problem constants
#define TT     1024
#define DD     4
#define PP     8
#define DPW    32                    // D*P
#define SS     256                   // N * N_SAMPLE
#define LT     16                    // timesteps per chunk
#define NCHUNK 64                    // chunks along T (64*16 = 1024)
#define TBL    (TT*DPW)              // 32768 table elements
#define SZ     ((size_t)SS*TT*DPW)   // 8388608 elements per output tensor

// Scratch (static __device__ arrays — allocation-free)
__device__ float g_mean[TBL];
__device__ float g_sw[TBL];
__device__ float g_c0[TBL];
__device__ float g_amul[TT*DD];            // sigmoid(a_raw[t-1,d]), amul[0,*]=0
__device__ float g_A[NCHUNK*DD];           // per-chunk product of amul (s-independent)
__device__ float4 g_B[SS*NCHUNK*8];        // per-chunk local recursion end, 2 MB
__device__ float4 g_C[SS*NCHUNK*8];        // exclusive carries, 2 MB

// ---------------------------------------------------------------------------
// K0: precompute per-(t,dp) tables.  32768 threads, trivial.
// ---------------------------------------------------------------------------
__global__ void arma_precompute(const float* __restrict__ m,
                                const float* __restrict__ s_raw,
                                const float* __restrict__ a_raw,
                                const int*   __restrict__ dim_idx)
{
    int idx = blockIdx.x * blockDim.x + threadIdx.x;
    if (idx >= TBL) return;
    int t  = idx >> 5;
    int dp = idx & 31;
    int dd = dp >> 3;
    int p  = dp & 7;
    int src = dim_idx[dd];

    float am = 0.0f;
    if (t > 0) {
        float x = a_raw[(t - 1) * DD + src];
        am = 1.0f / (1.0f + expf(-x));
    }

    float sv = s_raw[t * DPW + src * PP + p];
    float sw = (sv > 20.0f) ? sv : log1pf(expf(sv));
    float mn = (1.0f - am) * m[t * DPW + src * PP + p];

    g_mean[idx] = mn;
    g_sw[idx]   = sw;
    g_c0[idx]   = -logf(sw) - 0.91893853320467274178f;  // -log(sw) - 0.5*log(2pi)
    if (p == 0) g_amul[t * DD + dd] = am;
}

// ---------------------------------------------------------------------------
// K0b: per-chunk products of amul.  NCHUNK*DD = 256 threads.
// ---------------------------------------------------------------------------
__global__ void arma_chunkprod()
{
    int idx = threadIdx.x;           // 0..255
    int c  = idx >> 2;
    int dd = idx & 3;
    float a = 1.0f;
    int t0 = c << 4;
#pragma unroll
    for (int i = 0; i < LT; i++)
        a *= g_amul[((t0 + i) << 2) + dd];
    g_A[(c << 2) + dd] = a;
}

// ---------------------------------------------------------------------------
// P1: stream noise once (float4), write lp, emit per-chunk summaries b.
// Grid: 512 blocks (s, half) x 256 threads (32 chunks x 8 quads).
// ---------------------------------------------------------------------------
__global__ void __launch_bounds__(256)
arma_pass1(const float4* __restrict__ noise4,
           float4* __restrict__ lp4,
           int write_lp)
{
    const int s     = blockIdx.x >> 1;
    const int half  = blockIdx.x & 1;
    const int q     = threadIdx.x & 7;            // dp quad: dp = 4q..4q+3
    const int chunk = (half << 5) + (threadIdx.x >> 3);
    const int dd    = q >> 1;
    const int t0    = chunk << 4;

    const float4* tbl_sw = (const float4*)g_sw;
    const float4* tbl_mn = (const float4*)g_mean;
    const float4* tbl_c0 = (const float4*)g_c0;

    const size_t base = ((size_t)((s << 10) + t0) << 3) + q;   // float4 index

    float4 b = make_float4(0.f, 0.f, 0.f, 0.f);

#pragma unroll
    for (int i = 0; i < LT; i++) {
        const int t  = t0 + i;
        const int ti = (t << 3) + q;
        const float4 n = __ldcs(&noise4[base + (size_t)i * 8]);
        if (write_lp) {
            const float4 c0 = tbl_c0[ti];
            float4 lp;
            lp.x = fmaf(-0.5f * n.x, n.x, c0.x);
            lp.y = fmaf(-0.5f * n.y, n.y, c0.y);
            lp.z = fmaf(-0.5f * n.z, n.z, c0.z);
            lp.w = fmaf(-0.5f * n.w, n.w, c0.w);
            __stcs(&lp4[base + (size_t)i * 8], lp);
        }
        const float4 sw = tbl_sw[ti];
        const float4 mn = tbl_mn[ti];
        const float am  = g_amul[(t << 2) + dd];
        b.x = fmaf(am, b.x, fmaf(sw.x, n.x, mn.x));
        b.y = fmaf(am, b.y, fmaf(sw.y, n.y, mn.y));
        b.z = fmaf(am, b.z, fmaf(sw.z, n.z, mn.z));
        b.w = fmaf(am, b.w, fmaf(sw.w, n.w, mn.w));
    }
    g_B[(((size_t)s << 6) + chunk) * 8 + q] = b;
}

// ---------------------------------------------------------------------------
// P2: exclusive affine scan over 64 chunk summaries per chain.
// Grid: 256 blocks (one per s) x 32 threads (one per dp chain).
// ---------------------------------------------------------------------------
__global__ void arma_scan()
{
    const int s  = blockIdx.x;
    const int dp = threadIdx.x;
    const int dd = dp >> 3;
    const float* B = (const float*)g_B + ((size_t)s << 6) * 32;   // [64][32]
    float*       C = (float*)g_C       + ((size_t)s << 6) * 32;

    float carry = 0.0f;
#pragma unroll
    for (int c = 0; c < NCHUNK; c++) {
        C[c * 32 + dp] = carry;
        carry = fmaf(g_A[(c << 2) + dd], carry, B[c * 32 + dp]);
    }
}

// ---------------------------------------------------------------------------
// P3: replay recursion with correct carries; noise re-read is an L2 hit.
// Same geometry as P1.
// ---------------------------------------------------------------------------
__global__ void __launch_bounds__(256)
arma_pass2(const float4* __restrict__ noise4,
           float4* __restrict__ param4)
{
    const int s     = blockIdx.x >> 1;
    const int half  = blockIdx.x & 1;
    const int q     = threadIdx.x & 7;
    const int chunk = (half << 5) + (threadIdx.x >> 3);
    const int dd    = q >> 1;
    const int t0    = chunk << 4;

    const float4* tbl_sw = (const float4*)g_sw;
    const float4* tbl_mn = (const float4*)g_mean;

    const size_t base = ((size_t)((s << 10) + t0) << 3) + q;

    float4 pv = g_C[(((size_t)s << 6) + chunk) * 8 + q];

#pragma unroll
    for (int i = 0; i < LT; i++) {
        const int t  = t0 + i;
        const int ti = (t << 3) + q;
        const float4 n  = noise4[base + (size_t)i * 8];   // L2 hit (read in P1)
        const float4 sw = tbl_sw[ti];
        const float4 mn = tbl_mn[ti];
        const float am  = g_amul[(t << 2) + dd];
        pv.x = fmaf(am, pv.x, fmaf(sw.x, n.x, mn.x));
        pv.y = fmaf(am, pv.y, fmaf(sw.y, n.y, mn.y));
        pv.z = fmaf(am, pv.z, fmaf(sw.z, n.z, mn.z));
        pv.w = fmaf(am, pv.w, fmaf(sw.w, n.w, mn.w));
        __stcs(&param4[base + (size_t)i * 8], pv);
    }
}

// ---------------------------------------------------------------------------
// Launch.  Inputs: 0:y 1:age 2:m 3:s_raw 4:a_raw 5:noise 6:cond_sample
//                  7:dim_idx 8:compute_log_prob
// Output: param (S,T,D,P) then log_prob (S,T,D,P), float32.
// ---------------------------------------------------------------------------
extern "C" void kernel_launch(void* const* d_in, const int* in_sizes, int n_in,
                              void* d_out, int out_size)
{
    const float* m      = (const float*)d_in[2];
    const float* s_raw  = (const float*)d_in[3];
    const float* a_raw  = (const float*)d_in[4];
    const float* noise  = (const float*)d_in[5];
    const int*   dimidx = (const int*)  d_in[7];

    float* out_param = (float*)d_out;
    int write_lp = (out_size >= (int)(2 * SZ)) ? 1 : 0;
    float* out_lp = out_param + SZ;

    const float4* noise4 = (const float4*)noise;
    float4* param4 = (float4*)out_param;
    float4* lp4    = (float4*)(write_lp ? out_lp : out_param);

    arma_precompute<<<(TBL + 255) / 256, 256>>>(m, s_raw, a_raw, dimidx);
    arma_chunkprod<<<1, 256>>>();
    arma_pass1<<<SS * 2, 256>>>(noise4, lp4, write_lp);
    arma_scan<<<SS, 32>>>();
    arma_pass2<<<SS * 2, 256>>>(noise4, param4);
}

// round 3
// speedup vs baseline: 1.5826x; 1.4065x over previous
#include <cuda_runtime.h>
#include <cuda_bf16.h>
#include <math.h>

// Problem constants
#define TT     1024
#define DD     4
#define PP     8
#define DPW    32                    // D*P
#define SS     256                   // N * N_SAMPLE
#define LT     16                    // timesteps per chunk
#define NCHUNK 64                    // chunks along T (64*16 = 1024)
#define TBL    (TT*DPW)              // 32768 table elements
#define SZ     ((size_t)SS*TT*DPW)   // 8388608 elements per output tensor

// Scratch (static __device__ arrays — allocation-free)
__device__ float  g_mean[TBL];
__device__ float  g_sw[TBL];
__device__ float  g_c0[TBL];
__device__ float  g_amul[TT*DD];          // sigmoid(a_raw[t-1,d]), amul[0,*]=0
__device__ float4 g_C[SS*NCHUNK*8];       // exclusive carries per chunk, 2 MB

// ---------------------------------------------------------------------------
// K0: precompute per-(t,dp) tables.  32768 threads, trivial.
// ---------------------------------------------------------------------------
__global__ void arma_precompute(const float* __restrict__ m,
                                const float* __restrict__ s_raw,
                                const float* __restrict__ a_raw,
                                const int*   __restrict__ dim_idx)
{
    int idx = blockIdx.x * blockDim.x + threadIdx.x;
    if (idx >= TBL) return;
    int t  = idx >> 5;
    int dp = idx & 31;
    int dd = dp >> 3;
    int p  = dp & 7;
    int src = dim_idx[dd];

    float am = 0.0f;
    if (t > 0) {
        float x = a_raw[(t - 1) * DD + src];
        am = 1.0f / (1.0f + expf(-x));
    }

    float sv = s_raw[t * DPW + src * PP + p];
    float sw = (sv > 20.0f) ? sv : log1pf(expf(sv));
    float mn = (1.0f - am) * m[t * DPW + src * PP + p];

    g_mean[idx] = mn;
    g_sw[idx]   = sw;
    g_c0[idx]   = -logf(sw) - 0.91893853320467274178f;  // -log(sw) - 0.5*log(2pi)
    if (p == 0) g_amul[t * DD + dd] = am;
}

// ---------------------------------------------------------------------------
// P1 (fused): one block per sample s; 512 threads = 64 chunks x 8 quads.
//  Phase A: stream noise (float4, default L2 policy), write lp, build
//           per-chunk affine summaries b.
//  Phase B: compute chunk products A (s-independent, cheap, in-block).
//  Phase C: 32 threads run the 64-step carry chain entirely in smem.
//  Phase D: write exclusive carries g_C (coalesced float4).
// ---------------------------------------------------------------------------
__global__ void __launch_bounds__(512)
arma_pass1(const float4* __restrict__ noise4,
           float4* __restrict__ lp4,
           int write_lp)
{
    const int s     = blockIdx.x;
    const int tid   = threadIdx.x;
    const int q     = tid & 7;            // dp quad: dp = 4q..4q+3
    const int chunk = tid >> 3;           // 0..63
    const int dd    = q >> 1;             // uniform within the quad
    const int t0    = chunk << 4;

    __shared__ float s_amul[TT * DD];     // 16 KB
    __shared__ float sB[NCHUNK][DPW];     // 8 KB  per-chunk local end values
    __shared__ float sA[NCHUNK][DD];      // 1 KB  per-chunk products of amul
    __shared__ float sC[NCHUNK][DPW];     // 8 KB  exclusive carries

    for (int i = tid; i < TT * DD; i += 512) s_amul[i] = g_amul[i];
    __syncthreads();

    const float4* tbl_sw = (const float4*)g_sw;
    const float4* tbl_mn = (const float4*)g_mean;
    const float4* tbl_c0 = (const float4*)g_c0;

    const size_t base = ((size_t)((s << 10) + t0) << 3) + q;   // float4 index

    float4 b = make_float4(0.f, 0.f, 0.f, 0.f);

#pragma unroll
    for (int i = 0; i < LT; i++) {
        const int t  = t0 + i;
        const int ti = (t << 3) + q;
        const float4 n = noise4[base + (size_t)i * 8];   // default policy: keep in L2 for P3
        if (write_lp) {
            const float4 c0 = tbl_c0[ti];
            float4 lp;
            lp.x = fmaf(-0.5f * n.x, n.x, c0.x);
            lp.y = fmaf(-0.5f * n.y, n.y, c0.y);
            lp.z = fmaf(-0.5f * n.z, n.z, c0.z);
            lp.w = fmaf(-0.5f * n.w, n.w, c0.w);
            __stcs(&lp4[base + (size_t)i * 8], lp);
        }
        const float4 sw = tbl_sw[ti];
        const float4 mn = tbl_mn[ti];
        const float am  = s_amul[(t << 2) + dd];
        b.x = fmaf(am, b.x, fmaf(sw.x, n.x, mn.x));
        b.y = fmaf(am, b.y, fmaf(sw.y, n.y, mn.y));
        b.z = fmaf(am, b.z, fmaf(sw.z, n.z, mn.z));
        b.w = fmaf(am, b.w, fmaf(sw.w, n.w, mn.w));
    }
    ((float4*)sB[chunk])[q] = b;

    // Phase B: per-chunk amul products (s-independent but trivial: 16 muls)
    if (tid < NCHUNK * DD) {
        const int c  = tid >> 2;
        const int d2 = tid & 3;
        float a = 1.0f;
        const int tb = c << 4;
#pragma unroll
        for (int i = 0; i < LT; i++)
            a *= s_amul[((tb + i) << 2) + d2];
        sA[c][d2] = a;
    }
    __syncthreads();

    // Phase C: serial affine scan in smem; 32 threads, one per dp chain.
    // Dependent chain is fma-only (4 cyc) — LDS operands are independent.
    if (tid < 32) {
        const int dp = tid;
        const int d2 = dp >> 3;
        float carry = 0.0f;
#pragma unroll
        for (int c = 0; c < NCHUNK; c++) {
            sC[c][dp] = carry;
            carry = fmaf(sA[c][d2], carry, sB[c][dp]);
        }
    }
    __syncthreads();

    // Phase D: coalesced carry writeback
    g_C[(((size_t)s << 6) + chunk) * 8 + q] = ((const float4*)sC[chunk])[q];
}

// ---------------------------------------------------------------------------
// P3: replay recursion with correct carries; noise re-read is an L2 hit.
// Grid: 512 blocks (s, half) x 256 threads.
// ---------------------------------------------------------------------------
__global__ void __launch_bounds__(256)
arma_pass2(const float4* __restrict__ noise4,
           float4* __restrict__ param4)
{
    const int s     = blockIdx.x >> 1;
    const int half  = blockIdx.x & 1;
    const int q     = threadIdx.x & 7;
    const int chunk = (half << 5) + (threadIdx.x >> 3);
    const int dd    = q >> 1;
    const int t0    = chunk << 4;

    const float4* tbl_sw = (const float4*)g_sw;
    const float4* tbl_mn = (const float4*)g_mean;

    const size_t base = ((size_t)((s << 10) + t0) << 3) + q;

    float4 pv = g_C[(((size_t)s << 6) + chunk) * 8 + q];

#pragma unroll
    for (int i = 0; i < LT; i++) {
        const int t  = t0 + i;
        const int ti = (t << 3) + q;
        const float4 n  = noise4[base + (size_t)i * 8];   // L2 hit (touched in P1)
        const float4 sw = tbl_sw[ti];
        const float4 mn = tbl_mn[ti];
        const float am  = g_amul[(t << 2) + dd];
        pv.x = fmaf(am, pv.x, fmaf(sw.x, n.x, mn.x));
        pv.y = fmaf(am, pv.y, fmaf(sw.y, n.y, mn.y));
        pv.z = fmaf(am, pv.z, fmaf(sw.z, n.z, mn.z));
        pv.w = fmaf(am, pv.w, fmaf(sw.w, n.w, mn.w));
        __stcs(&param4[base + (size_t)i * 8], pv);
    }
}

// ---------------------------------------------------------------------------
// Launch.  Inputs: 0:y 1:age 2:m 3:s_raw 4:a_raw 5:noise 6:cond_sample
//                  7:dim_idx 8:compute_log_prob
// Output: param (S,T,D,P) then log_prob (S,T,D,P), float32.
// ---------------------------------------------------------------------------
extern "C" void kernel_launch(void* const* d_in, const int* in_sizes, int n_in,
                              void* d_out, int out_size)
{
    const float* m      = (const float*)d_in[2];
    const float* s_raw  = (const float*)d_in[3];
    const float* a_raw  = (const float*)d_in[4];
    const float* noise  = (const float*)d_in[5];
    const int*   dimidx = (const int*)  d_in[7];

    float* out_param = (float*)d_out;
    int write_lp = (out_size >= (int)(2 * SZ)) ? 1 : 0;
    float* out_lp = out_param + SZ;

    const float4* noise4 = (const float4*)noise;
    float4* param4 = (float4*)out_param;
    float4* lp4    = (float4*)(write_lp ? out_lp : out_param);

    arma_precompute<<<(TBL + 255) / 256, 256>>>(m, s_raw, a_raw, dimidx);
    arma_pass1<<<SS, 512>>>(noise4, lp4, write_lp);
    arma_pass2<<<SS * 2, 256>>>(noise4, param4);
}

// round 4
// speedup vs baseline: 1.7199x; 1.0868x over previous
#include <cuda_runtime.h>
#include <cuda_bf16.h>
#include <math.h>

// Problem constants
#define TT     1024
#define DD     4
#define PP     8
#define DPW    32                    // D*P
#define SS     256                   // N * N_SAMPLE
#define LT     16                    // timesteps per chunk
#define NCHUNK 64                    // chunks along T (64*16 = 1024)
#define TBL    (TT*DPW)              // 32768 table elements
#define SZ     ((size_t)SS*TT*DPW)   // 8388608 elements per output tensor

// Precomputed per-(t,dp) tables (allocation-free scratch)
__device__ float g_mean[TBL];
__device__ float g_sw[TBL];
__device__ float g_c0[TBL];
__device__ float g_amul[TT*DD];      // sigmoid(a_raw[t-1,d]), amul[0,*]=0

// ---------------------------------------------------------------------------
// K0: precompute per-(t,dp) tables. Fast-math intrinsics (rel-err budget is
// 1e-3; these are ~1e-6). 256 blocks x 128 threads for SM spread.
// ---------------------------------------------------------------------------
__global__ void arma_precompute(const float* __restrict__ m,
                                const float* __restrict__ s_raw,
                                const float* __restrict__ a_raw,
                                const int*   __restrict__ dim_idx)
{
    int idx = blockIdx.x * blockDim.x + threadIdx.x;
    if (idx >= TBL) return;
    int t  = idx >> 5;
    int dp = idx & 31;
    int dd = dp >> 3;
    int p  = dp & 7;
    int src = dim_idx[dd];

    float am = 0.0f;
    if (t > 0) {
        float x = a_raw[(t - 1) * DD + src];
        am = 1.0f / (1.0f + __expf(-x));
    }

    float sv = s_raw[t * DPW + src * PP + p];
    // softplus(sv) = log(1 + e^sv); inputs are ~ -6 +- 0.3, safe for fast path
    float sw = (sv > 20.0f) ? sv : __logf(1.0f + __expf(sv));
    float mn = (1.0f - am) * m[t * DPW + src * PP + p];

    g_mean[idx] = mn;
    g_sw[idx]   = sw;
    g_c0[idx]   = -__logf(sw) - 0.91893853320467274178f;  // -log(sw)-0.5*log(2pi)
    if (p == 0) g_amul[t * DD + dd] = am;
}

// ---------------------------------------------------------------------------
// Fused main kernel: one block per sample s; 512 threads = 64 chunks x 8 quads.
//  Phase A: stream noise (float4), write lp (__stcs), build z[16] in regs and
//           the per-chunk affine summary b.
//  Phase B: per-chunk amul products (in-block, trivial).
//  Phase C: 32 threads run the 64-step carry chain in smem (fma-latency only).
//  Phase D: replay recursion from registers, write param (__stcs).
// Single read of noise, single read of tables, no scratch round trip.
// ---------------------------------------------------------------------------
__global__ void __launch_bounds__(512, 1)
arma_fused(const float4* __restrict__ noise4,
           float4* __restrict__ param4,
           float4* __restrict__ lp4,
           int write_lp)
{
    const int s     = blockIdx.x;
    const int tid   = threadIdx.x;
    const int q     = tid & 7;            // dp quad: dp = 4q..4q+3
    const int chunk = tid >> 3;           // 0..63
    const int dd    = q >> 1;             // output dim, uniform in quad
    const int t0    = chunk << 4;

    __shared__ float s_amul[TT * DD];     // 16 KB
    __shared__ float sB[NCHUNK][DPW];     // 8 KB  per-chunk local end values
    __shared__ float sA[NCHUNK][DD];      // 1 KB  per-chunk amul products
    __shared__ float sC[NCHUNK][DPW];     // 8 KB  exclusive carries

    for (int i = tid; i < TT * DD; i += 512) s_amul[i] = g_amul[i];
    __syncthreads();

    const float4* tbl_sw = (const float4*)g_sw;
    const float4* tbl_mn = (const float4*)g_mean;
    const float4* tbl_c0 = (const float4*)g_c0;

    const size_t base = ((size_t)((s << 10) + t0) << 3) + q;   // float4 index

    float4 z[LT];
    float4 b = make_float4(0.f, 0.f, 0.f, 0.f);

#pragma unroll
    for (int i = 0; i < LT; i++) {
        const int t  = t0 + i;
        const int ti = (t << 3) + q;
        const float4 n = noise4[base + (size_t)i * 8];
        const float4 sw = tbl_sw[ti];
        const float4 mn = tbl_mn[ti];
        float4 zz;
        zz.x = fmaf(sw.x, n.x, mn.x);
        zz.y = fmaf(sw.y, n.y, mn.y);
        zz.z = fmaf(sw.z, n.z, mn.z);
        zz.w = fmaf(sw.w, n.w, mn.w);
        z[i] = zz;
        if (write_lp) {
            const float4 c0 = tbl_c0[ti];
            float4 lp;
            lp.x = fmaf(-0.5f * n.x, n.x, c0.x);
            lp.y = fmaf(-0.5f * n.y, n.y, c0.y);
            lp.z = fmaf(-0.5f * n.z, n.z, c0.z);
            lp.w = fmaf(-0.5f * n.w, n.w, c0.w);
            __stcs(&lp4[base + (size_t)i * 8], lp);
        }
        const float am = s_amul[(t << 2) + dd];
        b.x = fmaf(am, b.x, zz.x);
        b.y = fmaf(am, b.y, zz.y);
        b.z = fmaf(am, b.z, zz.z);
        b.w = fmaf(am, b.w, zz.w);
    }
    ((float4*)sB[chunk])[q] = b;

    // Phase B: per-chunk amul products (s-independent, 16 muls per thread)
    if (tid < NCHUNK * DD) {
        const int c  = tid >> 2;
        const int d2 = tid & 3;
        float a = 1.0f;
        const int tb = c << 4;
#pragma unroll
        for (int i = 0; i < LT; i++)
            a *= s_amul[((tb + i) << 2) + d2];
        sA[c][d2] = a;
    }
    __syncthreads();

    // Phase C: serial affine scan; 32 threads, one per dp chain.
    if (tid < 32) {
        const int dp = tid;
        const int d2 = dp >> 3;
        float carry = 0.0f;
#pragma unroll
        for (int c = 0; c < NCHUNK; c++) {
            sC[c][dp] = carry;
            carry = fmaf(sA[c][d2], carry, sB[c][dp]);
        }
    }
    __syncthreads();

    // Phase D: replay recursion from registers with correct carry-in.
    float4 pv = ((const float4*)sC[chunk])[q];
#pragma unroll
    for (int i = 0; i < LT; i++) {
        const int t = t0 + i;
        const float am = s_amul[(t << 2) + dd];
        pv.x = fmaf(am, pv.x, z[i].x);
        pv.y = fmaf(am, pv.y, z[i].y);
        pv.z = fmaf(am, pv.z, z[i].z);
        pv.w = fmaf(am, pv.w, z[i].w);
        __stcs(&param4[base + (size_t)i * 8], pv);
    }
}

// ---------------------------------------------------------------------------
// Launch.  Inputs: 0:y 1:age 2:m 3:s_raw 4:a_raw 5:noise 6:cond_sample
//                  7:dim_idx 8:compute_log_prob
// Output: param (S,T,D,P) then log_prob (S,T,D,P), float32.
// ---------------------------------------------------------------------------
extern "C" void kernel_launch(void* const* d_in, const int* in_sizes, int n_in,
                              void* d_out, int out_size)
{
    const float* m      = (const float*)d_in[2];
    const float* s_raw  = (const float*)d_in[3];
    const float* a_raw  = (const float*)d_in[4];
    const float* noise  = (const float*)d_in[5];
    const int*   dimidx = (const int*)  d_in[7];

    float* out_param = (float*)d_out;
    int write_lp = (out_size >= (int)(2 * SZ)) ? 1 : 0;
    float* out_lp = out_param + SZ;

    const float4* noise4 = (const float4*)noise;
    float4* param4 = (float4*)out_param;
    float4* lp4    = (float4*)(write_lp ? out_lp : out_param);

    arma_precompute<<<256, 128>>>(m, s_raw, a_raw, dimidx);
    arma_fused<<<SS, 512>>>(noise4, param4, lp4, write_lp);
}

// round 5
// speedup vs baseline: 1.7724x; 1.0305x over previous
#include <cuda_runtime.h>
#include <cuda_bf16.h>
#include <math.h>

// Problem constants
#define TT     1024
#define DD     4
#define PP     8
#define DPW    32                    // D*P
#define SS     256                   // N * N_SAMPLE
#define LT     16                    // timesteps per chunk
#define NCHUNK 64                    // chunks along T (64*16 = 1024)
#define TBL    (TT*DPW)              // 32768 table elements
#define SZ     ((size_t)SS*TT*DPW)   // 8388608 elements per output tensor

// Precomputed per-(t,dp) tables (allocation-free scratch)
__device__ float g_mean[TBL];
__device__ float g_sw[TBL];
__device__ float g_c0[TBL];
__device__ float g_amul[TT*DD];      // sigmoid(a_raw[t-1,d]), amul[0,*]=0

// ---------------------------------------------------------------------------
// K0: precompute per-(t,dp) tables. Fast-math intrinsics; one elem per thread.
// ---------------------------------------------------------------------------
__global__ void arma_precompute(const float* __restrict__ m,
                                const float* __restrict__ s_raw,
                                const float* __restrict__ a_raw,
                                const int*   __restrict__ dim_idx)
{
    int idx = blockIdx.x * blockDim.x + threadIdx.x;
    if (idx >= TBL) return;
    int t  = idx >> 5;
    int dp = idx & 31;
    int dd = dp >> 3;
    int p  = dp & 7;
    int src = dim_idx[dd];

    float am = 0.0f;
    if (t > 0) {
        float x = a_raw[(t - 1) * DD + src];
        am = 1.0f / (1.0f + __expf(-x));
    }

    float sv = s_raw[t * DPW + src * PP + p];
    float sw = (sv > 20.0f) ? sv : __logf(1.0f + __expf(sv));   // softplus
    float mn = (1.0f - am) * m[t * DPW + src * PP + p];

    g_mean[idx] = mn;
    g_sw[idx]   = sw;
    g_c0[idx]   = -__logf(sw) - 0.91893853320467274178f;  // -log(sw)-0.5*log(2pi)
    if (p == 0) g_amul[t * DD + dd] = am;
}

// ---------------------------------------------------------------------------
// Fused main kernel: one block per sample s; 512 threads = 64 chunks x 8 quads.
//  Phase A: stream noise (float4); write lp (__stcs, never re-read); run the
//           ZERO-CARRY local recursion, storing local values into param4
//           (default policy -> L2 resident; re-read in Phase D).
//  Phase B: per-chunk amul products.
//  Phase C: 32 threads run the 64-step carry chain in smem.
//  Phase D: final_i = local_i + Q_i * carry, where Q_i = running amul product
//           (recomputed from smem, ~1 mul/step). Re-read param4 (L2 hit),
//           final store with __stcs.
// No z[] register array -> ~50 regs -> 2 blocks/SM -> single wave.
// ---------------------------------------------------------------------------
__global__ void __launch_bounds__(512, 2)
arma_fused(const float4* __restrict__ noise4,
           float4* __restrict__ param4,
           float4* __restrict__ lp4,
           int write_lp)
{
    const int s     = blockIdx.x;
    const int tid   = threadIdx.x;
    const int q     = tid & 7;            // dp quad: dp = 4q..4q+3
    const int chunk = tid >> 3;           // 0..63
    const int dd    = q >> 1;             // output dim, uniform in quad
    const int t0    = chunk << 4;

    __shared__ float s_amul[TT * DD];     // 16 KB
    __shared__ float sB[NCHUNK][DPW];     // 8 KB  per-chunk local end values
    __shared__ float sA[NCHUNK][DD];      // 1 KB  per-chunk amul products
    __shared__ float sC[NCHUNK][DPW];     // 8 KB  exclusive carries

    for (int i = tid; i < TT * DD; i += 512) s_amul[i] = g_amul[i];
    __syncthreads();

    const float4* tbl_sw = (const float4*)g_sw;
    const float4* tbl_mn = (const float4*)g_mean;
    const float4* tbl_c0 = (const float4*)g_c0;

    const size_t base = ((size_t)((s << 10) + t0) << 3) + q;   // float4 index

    // ---- Phase A: local (zero-carry) recursion, store locals to param4 ----
    float4 loc = make_float4(0.f, 0.f, 0.f, 0.f);

#pragma unroll
    for (int i = 0; i < LT; i++) {
        const int t  = t0 + i;
        const int ti = (t << 3) + q;
        const float4 n  = noise4[base + (size_t)i * 8];
        const float4 sw = tbl_sw[ti];
        const float4 mn = tbl_mn[ti];
        if (write_lp) {
            const float4 c0 = tbl_c0[ti];
            float4 lp;
            lp.x = fmaf(-0.5f * n.x, n.x, c0.x);
            lp.y = fmaf(-0.5f * n.y, n.y, c0.y);
            lp.z = fmaf(-0.5f * n.z, n.z, c0.z);
            lp.w = fmaf(-0.5f * n.w, n.w, c0.w);
            __stcs(&lp4[base + (size_t)i * 8], lp);
        }
        const float am = s_amul[(t << 2) + dd];
        loc.x = fmaf(am, loc.x, fmaf(sw.x, n.x, mn.x));
        loc.y = fmaf(am, loc.y, fmaf(sw.y, n.y, mn.y));
        loc.z = fmaf(am, loc.z, fmaf(sw.z, n.z, mn.z));
        loc.w = fmaf(am, loc.w, fmaf(sw.w, n.w, mn.w));
        param4[base + (size_t)i * 8] = loc;   // default policy: keep in L2
    }
    ((float4*)sB[chunk])[q] = loc;            // chunk-end local value

    // ---- Phase B: per-chunk amul products (s-independent, trivial) ----
    if (tid < NCHUNK * DD) {
        const int c  = tid >> 2;
        const int d2 = tid & 3;
        float a = 1.0f;
        const int tb = c << 4;
#pragma unroll
        for (int i = 0; i < LT; i++)
            a *= s_amul[((tb + i) << 2) + d2];
        sA[c][d2] = a;
    }
    __syncthreads();

    // ---- Phase C: serial affine scan; 32 threads, one per dp chain ----
    if (tid < 32) {
        const int dp = tid;
        const int d2 = dp >> 3;
        float carry = 0.0f;
#pragma unroll
        for (int c = 0; c < NCHUNK; c++) {
            sC[c][dp] = carry;
            carry = fmaf(sA[c][d2], carry, sB[c][dp]);
        }
    }
    __syncthreads();

    // ---- Phase D: final = local + Q * carry (locals re-read from L2) ----
    const float4 carry = ((const float4*)sC[chunk])[q];
    float Q = 1.0f;
#pragma unroll
    for (int i = 0; i < LT; i++) {
        const int t = t0 + i;
        const float am = s_amul[(t << 2) + dd];
        Q *= am;
        const float4 lv = param4[base + (size_t)i * 8];   // L2 hit
        float4 outv;
        outv.x = fmaf(Q, carry.x, lv.x);
        outv.y = fmaf(Q, carry.y, lv.y);
        outv.z = fmaf(Q, carry.z, lv.z);
        outv.w = fmaf(Q, carry.w, lv.w);
        __stcs(&param4[base + (size_t)i * 8], outv);
    }
}

// ---------------------------------------------------------------------------
// Launch.  Inputs: 0:y 1:age 2:m 3:s_raw 4:a_raw 5:noise 6:cond_sample
//                  7:dim_idx 8:compute_log_prob
// Output: param (S,T,D,P) then log_prob (S,T,D,P), float32.
// ---------------------------------------------------------------------------
extern "C" void kernel_launch(void* const* d_in, const int* in_sizes, int n_in,
                              void* d_out, int out_size)
{
    const float* m      = (const float*)d_in[2];
    const float* s_raw  = (const float*)d_in[3];
    const float* a_raw  = (const float*)d_in[4];
    const float* noise  = (const float*)d_in[5];
    const int*   dimidx = (const int*)  d_in[7];

    float* out_param = (float*)d_out;
    int write_lp = (out_size >= (int)(2 * SZ)) ? 1 : 0;
    float* out_lp = out_param + SZ;

    const float4* noise4 = (const float4*)noise;
    float4* param4 = (float4*)out_param;
    float4* lp4    = (float4*)(write_lp ? out_lp : out_param);

    arma_precompute<<<128, 256>>>(m, s_raw, a_raw, dimidx);
    arma_fused<<<SS, 512>>>(noise4, param4, lp4, write_lp);
}